// round 16
// baseline (speedup 1.0000x reference)
#include <cuda_runtime.h>
#include <cuda_fp16.h>
#include <math.h>
#include <stdint.h>

#define BB 2
#define SS 1024
#define HID 768
#define HH 12
#define DD 64
#define NORM_INV 0.125f        // 1/sqrt(64)
#define LOG2E    1.44269504f
#define LOG2E_8  0.18033688f   // log2(e)/8

// scratch
__device__ __half g_q[BB*HH*SS*DD];       // pre-scaled by log2e/8
__device__ __half g_k[BB*HH*SS*DD];
__device__ __half g_v[BB*HH*SS*DD];       // [B,H,D,S] transposed
__device__ __half g_ah[BB*SS*HID];        // hidden_states as half
__device__ __half g_wh[3*HID*HID];        // Wq|Wk|Wv as half
__device__ __half g_bias[(size_t)BB*HH*SS*SS];  // log2e*((rel1+rel2)/8 + amask)

// ---------------- helpers ---------------------------------------------------
__device__ __forceinline__ void mma_f16(float* c, uint32_t a0, uint32_t a1,
                                        uint32_t a2, uint32_t a3,
                                        uint32_t b0, uint32_t b1) {
    asm volatile(
        "mma.sync.aligned.m16n8k16.row.col.f32.f16.f16.f32 "
        "{%0,%1,%2,%3},{%4,%5,%6,%7},{%8,%9},{%0,%1,%2,%3};\n"
        : "+f"(c[0]), "+f"(c[1]), "+f"(c[2]), "+f"(c[3])
        : "r"(a0), "r"(a1), "r"(a2), "r"(a3), "r"(b0), "r"(b1));
}
__device__ __forceinline__ void ldsm4(uint32_t* r, uint32_t a) {
    asm volatile("ldmatrix.sync.aligned.m8n8.x4.shared.b16 {%0,%1,%2,%3},[%4];\n"
                 : "=r"(r[0]), "=r"(r[1]), "=r"(r[2]), "=r"(r[3]) : "r"(a));
}
__device__ __forceinline__ void ldsm4t(uint32_t* r, uint32_t a) {
    asm volatile("ldmatrix.sync.aligned.m8n8.x4.trans.shared.b16 {%0,%1,%2,%3},[%4];\n"
                 : "=r"(r[0]), "=r"(r[1]), "=r"(r[2]), "=r"(r[3]) : "r"(a));
}
__device__ __forceinline__ uint32_t packh2(float x, float y) {
    __half2 h = __floats2half2_rn(x, y);
    return *(uint32_t*)&h;
}
__device__ __forceinline__ float ex2(float x) {
    float r;
    asm("ex2.approx.ftz.f32 %0, %1;" : "=f"(r) : "f"(x));
    return r;
}
__device__ __forceinline__ uint32_t smaddr(const void* p) {
    return (uint32_t)__cvta_generic_to_shared(p);
}
__device__ __forceinline__ void cpa16(uint32_t d, const void* s) {
    asm volatile("cp.async.cg.shared.global [%0],[%1],16;\n" :: "r"(d), "l"(s));
}
#define CP_COMMIT() asm volatile("cp.async.commit_group;\n")
#define CP_WAIT(n)  asm volatile("cp.async.wait_group %0;\n" :: "n"(n))

// ---------------- fp32 -> fp16 pre-pass (hs, W) -----------------------------
__global__ __launch_bounds__(256) void to_half(
    const float* __restrict__ hs, const float* __restrict__ Wq,
    const float* __restrict__ Wk, const float* __restrict__ Wv)
{
    const int which = blockIdx.y;
    const float* src = (which == 0) ? hs : (which == 1) ? Wq : (which == 2) ? Wk : Wv;
    __half* dst = (which == 0) ? g_ah : g_wh + (size_t)(which - 1) * HID * HID;
    const int n4 = (which == 0) ? (BB * SS * HID / 4) : (HID * HID / 4);
    for (int i = blockIdx.x * 256 + threadIdx.x; i < n4; i += gridDim.x * 256) {
        float4 v = ((const float4*)src)[i];
        ((__half2*)dst)[2 * i + 0] = __floats2half2_rn(v.x, v.y);
        ((__half2*)dst)[2 * i + 1] = __floats2half2_rn(v.z, v.w);
    }
}

// ---------------- merged: QKV projection (blocks < 288) ∥ bias prep --------
#define PROJ_BLOCKS 288
#define PREP_BLOCKS 3072
#define PREP_ITERS  4
#define PAOFF 18432
#define PSTG  35840

__global__ __launch_bounds__(256) void proj_prep(
    const float* __restrict__ bq, const float* __restrict__ bk,
    const float* __restrict__ bv,
    const float* __restrict__ rel1, const float* __restrict__ rel2,
    const float* __restrict__ amask)
{
    const int t = threadIdx.x;

    if (blockIdx.x >= PROJ_BLOCKS) {
        // ---- bias prep: g_bias = log2e*((rel1+rel2)/8 + amask), fp16 ----
        const int pb = blockIdx.x - PROJ_BLOCKS;
        size_t i = (size_t)pb * 256 + t;                 // 8-elem chunk index
        const size_t stride = (size_t)PREP_BLOCKS * 256;
        #pragma unroll
        for (int k = 0; k < PREP_ITERS; k++, i += stride) {
            const size_t base = i * 8;
            int tcol = (int)(base & (SS - 1));
            int bidx = (int)(base / ((size_t)HH * SS * SS));
            float4 a0 = *(const float4*)(rel1 + base);
            float4 a1 = *(const float4*)(rel1 + base + 4);
            float4 c0 = *(const float4*)(rel2 + base);
            float4 c1 = *(const float4*)(rel2 + base + 4);
            float4 m0v = *(const float4*)(amask + (size_t)bidx * SS + tcol);
            float4 m1v = *(const float4*)(amask + (size_t)bidx * SS + tcol + 4);
            uint4 o;
            o.x = packh2((a0.x + c0.x) * LOG2E_8 + m0v.x * LOG2E,
                         (a0.y + c0.y) * LOG2E_8 + m0v.y * LOG2E);
            o.y = packh2((a0.z + c0.z) * LOG2E_8 + m0v.z * LOG2E,
                         (a0.w + c0.w) * LOG2E_8 + m0v.w * LOG2E);
            o.z = packh2((a1.x + c1.x) * LOG2E_8 + m1v.x * LOG2E,
                         (a1.y + c1.y) * LOG2E_8 + m1v.y * LOG2E);
            o.w = packh2((a1.z + c1.z) * LOG2E_8 + m1v.z * LOG2E,
                         (a1.w + c1.w) * LOG2E_8 + m1v.w * LOG2E);
            *(uint4*)(g_bias + base) = o;
        }
        return;
    }

    // ---- projection role (cp.async double-buffered) ----
    extern __shared__ char sm[];
    const uint32_t smem_u = smaddr(sm);

    const int which = blockIdx.x / 96;
    const int r = blockIdx.x % 96;
    const int m0 = (r / 6) * 128, n0 = (r % 6) * 128;

    const __half* Ah = g_ah;
    const __half* Wh = g_wh + (size_t)which * HID * HID;
    const float* bias = (which == 0) ? bq : (which == 1) ? bk : bv;

    const int lane = t & 31, w = t >> 5;

    float acc[16][4];
    #pragma unroll
    for (int i = 0; i < 16; i++)
        acc[i][0] = acc[i][1] = acc[i][2] = acc[i][3] = 0.f;

    const uint32_t a_lane = ((w * 16 + (lane & 15)) * 72 + (lane >> 4) * 8) * 2;
    const uint32_t b_lane = PAOFF +
        (((lane & 7) + ((lane >> 3) & 1) * 8) * 136 + (lane >> 4) * 8) * 2;

    auto prefetch = [&](int kt, int stg) {
        const uint32_t so = smem_u + stg * PSTG;
        #pragma unroll
        for (int i = 0; i < 4; i++) {
            int c = t + i * 256, row = c >> 3, o = c & 7;
            cpa16(so + row * 144 + o * 16,
                  Ah + (size_t)(m0 + row) * HID + kt * 64 + o * 8);
        }
        #pragma unroll
        for (int i = 0; i < 4; i++) {
            int c = t + i * 256, row = c >> 4, o = c & 15;
            cpa16(so + PAOFF + row * 272 + o * 16,
                  Wh + (size_t)(kt * 64 + row) * HID + n0 + o * 8);
        }
    };

    prefetch(0, 0);
    CP_COMMIT();

    for (int kt = 0; kt < HID / 64; kt++) {
        const int cur = kt & 1;
        if (kt + 1 < HID / 64) {
            prefetch(kt + 1, cur ^ 1);
            CP_COMMIT();
            CP_WAIT(1);
        } else {
            CP_WAIT(0);
        }
        __syncthreads();

        const uint32_t sb = smem_u + cur * PSTG;
        #pragma unroll
        for (int kk = 0; kk < 64; kk += 16) {
            uint32_t af[4];
            ldsm4(af, sb + a_lane + kk * 2);
            #pragma unroll
            for (int p = 0; p < 8; p++) {
                uint32_t bf[4];
                ldsm4t(bf, sb + b_lane + kk * 272 + p * 32);
                mma_f16(acc[2 * p],     af[0], af[1], af[2], af[3], bf[0], bf[1]);
                mma_f16(acc[2 * p + 1], af[0], af[1], af[2], af[3], bf[2], bf[3]);
            }
        }
        __syncthreads();
    }

    // q scaled by log2e/8 so scores are already in exp2 domain
    const float scale = (which == 0) ? LOG2E_8 : 1.f;
    const int r0 = m0 + w * 16 + (lane >> 2);
    const int q2 = (lane & 3) * 2;
    #pragma unroll
    for (int nf = 0; nf < 16; nf++) {
        int n = n0 + nf * 8 + q2;
        int h = n >> 6, d = n & 63;
        float bx = bias[n], by = bias[n + 1];
        #pragma unroll
        for (int hf = 0; hf < 2; hf++) {
            int m = r0 + hf * 8;
            int b_ = m >> 10, s = m & 1023;
            float vx = (acc[nf][hf * 2 + 0] + bx) * scale;
            float vy = (acc[nf][hf * 2 + 1] + by) * scale;
            __half2 hv = __floats2half2_rn(vx, vy);
            size_t bh = (size_t)b_ * HH + h;
            if (which == 2) {
                g_v[(bh * DD + d) * SS + s]     = __low2half(hv);
                g_v[(bh * DD + d + 1) * SS + s] = __high2half(hv);
            } else {
                __half* dst = ((which == 0) ? g_q : g_k) + (bh * SS + s) * DD + d;
                *(__half2*)dst = hv;
            }
        }
    }
}

// ---------------- flash attention: 3-stage ring, 1 barrier/tile ------------
// smem: Q 9216 | 3 stages x (K 9216 + V 9216 + bias 9216) = 92160 (2 CTA/SM)
// no-max softmax in exp2 domain; Q fragments hoisted to registers.
#define AQB   9216
#define ASTG2 27648
#define SMEM_ATTN (AQB + 3 * ASTG2)   // 92160

__global__ __launch_bounds__(128) void attn_kernel(
    const float* __restrict__ hmask, float* __restrict__ out)
{
    extern __shared__ char sm[];
    const uint32_t smem_u = smaddr(sm);

    const int t = threadIdx.x, lane = t & 31, w = t >> 5;
    const int bh = blockIdx.y, b = bh / HH, h = bh % HH;
    const int s0 = blockIdx.x * 64;

    // Q tile -> smem
    {
        int row = t >> 1, seg = t & 1;
        const uint4* src = (const uint4*)(g_q + ((size_t)bh * SS + s0 + row) * DD + seg * 32);
        uint4* dst = (uint4*)(sm + row * 144 + seg * 64);
        #pragma unroll
        for (int i = 0; i < 4; i++) dst[i] = src[i];
    }

    // one stage = K | V | bias, all 64 rows x 144B pitch
    auto prefetch = [&](int tt, int stg) {
        const uint32_t so = smem_u + AQB + stg * ASTG2;
        const int t64 = tt * 64;
        #pragma unroll
        for (int i = 0; i < 4; i++) {
            int c = t + i * 128, row = c >> 3, o = c & 7;
            cpa16(so + row * 144 + o * 16,
                  g_k + ((size_t)bh * SS + t64 + row) * DD + o * 8);
            cpa16(so + AQB + row * 144 + o * 16,
                  g_v + ((size_t)bh * DD + row) * SS + t64 + o * 8);
            cpa16(so + 2 * AQB + row * 144 + o * 16,
                  g_bias + ((size_t)bh * SS + s0 + row) * SS + t64 + o * 8);
        }
    };

    prefetch(0, 0);
    CP_COMMIT();
    prefetch(1, 1);
    CP_COMMIT();

    const uint32_t a_base = smem_u + ((w * 16 + (lane & 15)) * 72 + (lane >> 4) * 8) * 2;
    const uint32_t kv_lane = (((lane & 7) + (lane >> 4) * 8) * 72 + ((lane >> 3) & 1) * 8) * 2;

    __syncthreads();            // Q visible
    uint32_t qf[4][4];          // Q a-fragments, loaded once
    #pragma unroll
    for (int j = 0; j < 4; j++) ldsm4(qf[j], a_base + j * 32);

    float oacc[8][4];
    #pragma unroll
    for (int i = 0; i < 8; i++)
        oacc[i][0] = oacc[i][1] = oacc[i][2] = oacc[i][3] = 0.f;
    float l0 = 0.f, l1 = 0.f;

    const int rl0 = w * 16 + (lane >> 2);
    const int q2 = (lane & 3) * 2;

    for (int u = 0; u < 16; u++) {
        const int stg = u % 3;
        if (u < 15) { CP_WAIT(1); } else { CP_WAIT(0); }
        __syncthreads();        // all reads of stage (u-1)%3 are done CTA-wide
        if (u + 2 < 16) {       // refill stage (u+2)%3 == (u-1)%3 — safe now
            prefetch(u + 2, (u + 2) % 3);
            CP_COMMIT();
        }

        const uint32_t kb = smem_u + AQB + stg * ASTG2 + kv_lane;
        const uint32_t vb = kb + AQB;
        const __half* Bs = (const __half*)(sm + AQB + stg * ASTG2 + 2 * AQB);

        // S = Q @ K^T (exp2 domain)
        float sacc[8][4];
        #pragma unroll
        for (int i = 0; i < 8; i++)
            sacc[i][0] = sacc[i][1] = sacc[i][2] = sacc[i][3] = 0.f;
        #pragma unroll
        for (int j = 0; j < 4; j++) {
            #pragma unroll
            for (int p = 0; p < 4; p++) {
                uint32_t bf[4];
                ldsm4(bf, kb + p * 2304 + j * 32);
                mma_f16(sacc[2 * p],     qf[j][0], qf[j][1], qf[j][2], qf[j][3], bf[0], bf[1]);
                mma_f16(sacc[2 * p + 1], qf[j][0], qf[j][1], qf[j][2], qf[j][3], bf[2], bf[3]);
            }
        }

        // p = exp2(s + bias'); per-lane partial row sums only
        #pragma unroll
        for (int nf = 0; nf < 8; nf++) {
            int cc = q2 + nf * 8;
            float2 ba = __half22float2(*(const __half2*)&Bs[rl0 * 72 + cc]);
            float2 bb = __half22float2(*(const __half2*)&Bs[(rl0 + 8) * 72 + cc]);
            sacc[nf][0] = ex2(sacc[nf][0] + ba.x);
            sacc[nf][1] = ex2(sacc[nf][1] + ba.y);
            sacc[nf][2] = ex2(sacc[nf][2] + bb.x);
            sacc[nf][3] = ex2(sacc[nf][3] + bb.y);
            l0 += sacc[nf][0] + sacc[nf][1];
            l1 += sacc[nf][2] + sacc[nf][3];
        }

        // O += P @ V
        #pragma unroll
        for (int j = 0; j < 4; j++) {
            uint32_t pa0 = packh2(sacc[2 * j][0],     sacc[2 * j][1]);
            uint32_t pa1 = packh2(sacc[2 * j][2],     sacc[2 * j][3]);
            uint32_t pa2 = packh2(sacc[2 * j + 1][0], sacc[2 * j + 1][1]);
            uint32_t pa3 = packh2(sacc[2 * j + 1][2], sacc[2 * j + 1][3]);
            #pragma unroll
            for (int p = 0; p < 4; p++) {
                uint32_t bf[4];
                ldsm4(bf, vb + p * 2304 + j * 32);
                mma_f16(oacc[2 * p],     pa0, pa1, pa2, pa3, bf[0], bf[1]);
                mma_f16(oacc[2 * p + 1], pa0, pa1, pa2, pa3, bf[2], bf[3]);
            }
        }
    }

    // epilogue: reduce row sums, normalize, head_mask, write
    l0 += __shfl_xor_sync(0xffffffffu, l0, 1);
    l0 += __shfl_xor_sync(0xffffffffu, l0, 2);
    l1 += __shfl_xor_sync(0xffffffffu, l1, 1);
    l1 += __shfl_xor_sync(0xffffffffu, l1, 2);
    const float hm = hmask[h];
    const float i0 = hm / l0, i1 = hm / l1;
    const int sA = s0 + rl0;
    float* o0 = out + ((size_t)b * SS + sA) * HID + h * DD + q2;
    float* o1 = out + ((size_t)b * SS + sA + 8) * HID + h * DD + q2;
    #pragma unroll
    for (int nf = 0; nf < 8; nf++) {
        *(float2*)(o0 + nf * 8) = make_float2(oacc[nf][0] * i0, oacc[nf][1] * i0);
        *(float2*)(o1 + nf * 8) = make_float2(oacc[nf][2] * i1, oacc[nf][3] * i1);
    }
}

// ---------------- launch ----------------------------------------------------
extern "C" void kernel_launch(void* const* d_in, const int* in_sizes, int n_in,
                              void* d_out, int out_size)
{
    const float* hs    = (const float*)d_in[0];
    const float* amask = (const float*)d_in[1];
    const float* hmask = (const float*)d_in[2];
    const float* rel1  = (const float*)d_in[3];
    const float* rel2  = (const float*)d_in[4];
    const float* Wq    = (const float*)d_in[5];
    const float* bq    = (const float*)d_in[6];
    const float* Wk    = (const float*)d_in[7];
    const float* bk    = (const float*)d_in[8];
    const float* Wv    = (const float*)d_in[9];
    const float* bv    = (const float*)d_in[10];
    float* out = (float*)d_out;

    const int smem_proj = 2 * PSTG;              // 71680
    cudaFuncSetAttribute(proj_prep, cudaFuncAttributeMaxDynamicSharedMemorySize, smem_proj);
    cudaFuncSetAttribute(attn_kernel, cudaFuncAttributeMaxDynamicSharedMemorySize, SMEM_ATTN);

    to_half<<<dim3(768, 4), 256>>>(hs, Wq, Wk, Wv);

    proj_prep<<<PROJ_BLOCKS + PREP_BLOCKS, 256, smem_proj>>>(
        bq, bk, bv, rel1, rel2, amask);

    dim3 ga(SS / 64, BB * HH);                // (16,24)
    attn_kernel<<<ga, 128, SMEM_ATTN>>>(hmask, out);
}

// round 17
// speedup vs baseline: 1.1733x; 1.1733x over previous
#include <cuda_runtime.h>
#include <cuda_fp16.h>
#include <math.h>
#include <stdint.h>

#define BB 2
#define SS 1024
#define HID 768
#define HH 12
#define DD 64
#define NORM_INV 0.125f        // 1/sqrt(64)
#define LOG2E    1.44269504f
#define LOG2E_8  0.18033688f   // log2(e)/8

// scratch
__device__ __half g_q[BB*HH*SS*DD];       // pre-scaled by log2e/8
__device__ __half g_k[BB*HH*SS*DD];
__device__ __half g_v[BB*HH*SS*DD];       // [B,H,D,S] transposed
__device__ __half g_ah[BB*SS*HID];        // hidden_states as half
__device__ __half g_wh[3*HID*HID];        // Wq|Wk|Wv as half
__device__ __half g_bias[(size_t)BB*HH*SS*SS];  // log2e*((rel1+rel2)/8 + amask)

// ---------------- helpers ---------------------------------------------------
__device__ __forceinline__ void mma_f16(float* c, uint32_t a0, uint32_t a1,
                                        uint32_t a2, uint32_t a3,
                                        uint32_t b0, uint32_t b1) {
    asm volatile(
        "mma.sync.aligned.m16n8k16.row.col.f32.f16.f16.f32 "
        "{%0,%1,%2,%3},{%4,%5,%6,%7},{%8,%9},{%0,%1,%2,%3};\n"
        : "+f"(c[0]), "+f"(c[1]), "+f"(c[2]), "+f"(c[3])
        : "r"(a0), "r"(a1), "r"(a2), "r"(a3), "r"(b0), "r"(b1));
}
__device__ __forceinline__ void ldsm4(uint32_t* r, uint32_t a) {
    asm volatile("ldmatrix.sync.aligned.m8n8.x4.shared.b16 {%0,%1,%2,%3},[%4];\n"
                 : "=r"(r[0]), "=r"(r[1]), "=r"(r[2]), "=r"(r[3]) : "r"(a));
}
__device__ __forceinline__ void ldsm4t(uint32_t* r, uint32_t a) {
    asm volatile("ldmatrix.sync.aligned.m8n8.x4.trans.shared.b16 {%0,%1,%2,%3},[%4];\n"
                 : "=r"(r[0]), "=r"(r[1]), "=r"(r[2]), "=r"(r[3]) : "r"(a));
}
__device__ __forceinline__ uint32_t packh2(float x, float y) {
    __half2 h = __floats2half2_rn(x, y);
    return *(uint32_t*)&h;
}
__device__ __forceinline__ float ex2(float x) {
    float r;
    asm("ex2.approx.ftz.f32 %0, %1;" : "=f"(r) : "f"(x));
    return r;
}
__device__ __forceinline__ uint32_t smaddr(const void* p) {
    return (uint32_t)__cvta_generic_to_shared(p);
}
__device__ __forceinline__ void cpa16(uint32_t d, const void* s) {
    asm volatile("cp.async.cg.shared.global [%0],[%1],16;\n" :: "r"(d), "l"(s));
}
#define CP_COMMIT() asm volatile("cp.async.commit_group;\n")
#define CP_WAIT(n)  asm volatile("cp.async.wait_group %0;\n" :: "n"(n))

// ---------------- fp32 -> fp16 pre-pass (hs, W) -----------------------------
__global__ __launch_bounds__(256) void to_half(
    const float* __restrict__ hs, const float* __restrict__ Wq,
    const float* __restrict__ Wk, const float* __restrict__ Wv)
{
    const int which = blockIdx.y;
    const float* src = (which == 0) ? hs : (which == 1) ? Wq : (which == 2) ? Wk : Wv;
    __half* dst = (which == 0) ? g_ah : g_wh + (size_t)(which - 1) * HID * HID;
    const int n4 = (which == 0) ? (BB * SS * HID / 4) : (HID * HID / 4);
    for (int i = blockIdx.x * 256 + threadIdx.x; i < n4; i += gridDim.x * 256) {
        float4 v = ((const float4*)src)[i];
        ((__half2*)dst)[2 * i + 0] = __floats2half2_rn(v.x, v.y);
        ((__half2*)dst)[2 * i + 1] = __floats2half2_rn(v.z, v.w);
    }
}

// ---------------- merged: QKV projection (blocks < 288) ∥ bias prep --------
#define PROJ_BLOCKS 288
#define PREP_BLOCKS 3072
#define PREP_ITERS  4
#define PAOFF 18432
#define PSTG  35840

__global__ __launch_bounds__(256) void proj_prep(
    const float* __restrict__ bq, const float* __restrict__ bk,
    const float* __restrict__ bv,
    const float* __restrict__ rel1, const float* __restrict__ rel2,
    const float* __restrict__ amask)
{
    const int t = threadIdx.x;

    if (blockIdx.x >= PROJ_BLOCKS) {
        // ---- bias prep: g_bias = log2e*((rel1+rel2)/8 + amask), fp16 ----
        const int pb = blockIdx.x - PROJ_BLOCKS;
        size_t i = (size_t)pb * 256 + t;                 // 8-elem chunk index
        const size_t stride = (size_t)PREP_BLOCKS * 256;
        #pragma unroll
        for (int k = 0; k < PREP_ITERS; k++, i += stride) {
            const size_t base = i * 8;
            int tcol = (int)(base & (SS - 1));
            int bidx = (int)(base / ((size_t)HH * SS * SS));
            float4 a0 = *(const float4*)(rel1 + base);
            float4 a1 = *(const float4*)(rel1 + base + 4);
            float4 c0 = *(const float4*)(rel2 + base);
            float4 c1 = *(const float4*)(rel2 + base + 4);
            float4 m0v = *(const float4*)(amask + (size_t)bidx * SS + tcol);
            float4 m1v = *(const float4*)(amask + (size_t)bidx * SS + tcol + 4);
            uint4 o;
            o.x = packh2((a0.x + c0.x) * LOG2E_8 + m0v.x * LOG2E,
                         (a0.y + c0.y) * LOG2E_8 + m0v.y * LOG2E);
            o.y = packh2((a0.z + c0.z) * LOG2E_8 + m0v.z * LOG2E,
                         (a0.w + c0.w) * LOG2E_8 + m0v.w * LOG2E);
            o.z = packh2((a1.x + c1.x) * LOG2E_8 + m1v.x * LOG2E,
                         (a1.y + c1.y) * LOG2E_8 + m1v.y * LOG2E);
            o.w = packh2((a1.z + c1.z) * LOG2E_8 + m1v.z * LOG2E,
                         (a1.w + c1.w) * LOG2E_8 + m1v.w * LOG2E);
            *(uint4*)(g_bias + base) = o;
        }
        return;
    }

    // ---- projection role (cp.async double-buffered) ----
    extern __shared__ char sm[];
    const uint32_t smem_u = smaddr(sm);

    const int which = blockIdx.x / 96;
    const int r = blockIdx.x % 96;
    const int m0 = (r / 6) * 128, n0 = (r % 6) * 128;

    const __half* Ah = g_ah;
    const __half* Wh = g_wh + (size_t)which * HID * HID;
    const float* bias = (which == 0) ? bq : (which == 1) ? bk : bv;

    const int lane = t & 31, w = t >> 5;

    float acc[16][4];
    #pragma unroll
    for (int i = 0; i < 16; i++)
        acc[i][0] = acc[i][1] = acc[i][2] = acc[i][3] = 0.f;

    const uint32_t a_lane = ((w * 16 + (lane & 15)) * 72 + (lane >> 4) * 8) * 2;
    const uint32_t b_lane = PAOFF +
        (((lane & 7) + ((lane >> 3) & 1) * 8) * 136 + (lane >> 4) * 8) * 2;

    auto prefetch = [&](int kt, int stg) {
        const uint32_t so = smem_u + stg * PSTG;
        #pragma unroll
        for (int i = 0; i < 4; i++) {
            int c = t + i * 256, row = c >> 3, o = c & 7;
            cpa16(so + row * 144 + o * 16,
                  Ah + (size_t)(m0 + row) * HID + kt * 64 + o * 8);
        }
        #pragma unroll
        for (int i = 0; i < 4; i++) {
            int c = t + i * 256, row = c >> 4, o = c & 15;
            cpa16(so + PAOFF + row * 272 + o * 16,
                  Wh + (size_t)(kt * 64 + row) * HID + n0 + o * 8);
        }
    };

    prefetch(0, 0);
    CP_COMMIT();

    for (int kt = 0; kt < HID / 64; kt++) {
        const int cur = kt & 1;
        if (kt + 1 < HID / 64) {
            prefetch(kt + 1, cur ^ 1);
            CP_COMMIT();
            CP_WAIT(1);
        } else {
            CP_WAIT(0);
        }
        __syncthreads();

        const uint32_t sb = smem_u + cur * PSTG;
        #pragma unroll
        for (int kk = 0; kk < 64; kk += 16) {
            uint32_t af[4];
            ldsm4(af, sb + a_lane + kk * 2);
            #pragma unroll
            for (int p = 0; p < 8; p++) {
                uint32_t bf[4];
                ldsm4t(bf, sb + b_lane + kk * 272 + p * 32);
                mma_f16(acc[2 * p],     af[0], af[1], af[2], af[3], bf[0], bf[1]);
                mma_f16(acc[2 * p + 1], af[0], af[1], af[2], af[3], bf[2], bf[3]);
            }
        }
        __syncthreads();
    }

    // q scaled by log2e/8 so scores are already in exp2 domain
    const float scale = (which == 0) ? LOG2E_8 : 1.f;
    const int r0 = m0 + w * 16 + (lane >> 2);
    const int q2 = (lane & 3) * 2;
    #pragma unroll
    for (int nf = 0; nf < 16; nf++) {
        int n = n0 + nf * 8 + q2;
        int h = n >> 6, d = n & 63;
        float bx = bias[n], by = bias[n + 1];
        #pragma unroll
        for (int hf = 0; hf < 2; hf++) {
            int m = r0 + hf * 8;
            int b_ = m >> 10, s = m & 1023;
            float vx = (acc[nf][hf * 2 + 0] + bx) * scale;
            float vy = (acc[nf][hf * 2 + 1] + by) * scale;
            __half2 hv = __floats2half2_rn(vx, vy);
            size_t bh = (size_t)b_ * HH + h;
            if (which == 2) {
                g_v[(bh * DD + d) * SS + s]     = __low2half(hv);
                g_v[(bh * DD + d + 1) * SS + s] = __high2half(hv);
            } else {
                __half* dst = ((which == 0) ? g_q : g_k) + (bh * SS + s) * DD + d;
                *(__half2*)dst = hv;
            }
        }
    }
}

// ---------------- flash attention: R12 structure + exp2 + Q-hoist ----------
// smem: Q 9216 | 2 stages x (K 9216 + V 9216 + bias 9216) = 64512 (3 CTA/SM)
#define AQB   9216
#define ASTG2 27648
#define SMEM_ATTN (AQB + 2 * ASTG2)   // 64512

__global__ __launch_bounds__(128) void attn_kernel(
    const float* __restrict__ hmask, float* __restrict__ out)
{
    extern __shared__ char sm[];
    const uint32_t smem_u = smaddr(sm);

    const int t = threadIdx.x, lane = t & 31, w = t >> 5;
    const int bh = blockIdx.y, b = bh / HH, h = bh % HH;
    const int s0 = blockIdx.x * 64;

    // Q tile -> smem
    {
        int row = t >> 1, seg = t & 1;
        const uint4* src = (const uint4*)(g_q + ((size_t)bh * SS + s0 + row) * DD + seg * 32);
        uint4* dst = (uint4*)(sm + row * 144 + seg * 64);
        #pragma unroll
        for (int i = 0; i < 4; i++) dst[i] = src[i];
    }

    // one stage = K | V | bias, all 64 rows x 144B pitch
    auto prefetch = [&](int tt, int stg) {
        const uint32_t so = smem_u + AQB + stg * ASTG2;
        const int t64 = tt * 64;
        #pragma unroll
        for (int i = 0; i < 4; i++) {
            int c = t + i * 128, row = c >> 3, o = c & 7;
            cpa16(so + row * 144 + o * 16,
                  g_k + ((size_t)bh * SS + t64 + row) * DD + o * 8);
            cpa16(so + AQB + row * 144 + o * 16,
                  g_v + ((size_t)bh * DD + row) * SS + t64 + o * 8);
            cpa16(so + 2 * AQB + row * 144 + o * 16,
                  g_bias + ((size_t)bh * SS + s0 + row) * SS + t64 + o * 8);
        }
    };

    prefetch(0, 0);
    CP_COMMIT();

    const uint32_t a_base = smem_u + ((w * 16 + (lane & 15)) * 72 + (lane >> 4) * 8) * 2;
    const uint32_t kv_lane = (((lane & 7) + (lane >> 4) * 8) * 72 + ((lane >> 3) & 1) * 8) * 2;

    // Q fragments: loaded ONCE (Q visible after this barrier)
    __syncthreads();
    uint32_t qf[4][4];
    #pragma unroll
    for (int j = 0; j < 4; j++) ldsm4(qf[j], a_base + j * 32);

    float oacc[8][4];
    #pragma unroll
    for (int i = 0; i < 8; i++)
        oacc[i][0] = oacc[i][1] = oacc[i][2] = oacc[i][3] = 0.f;
    float l0 = 0.f, l1 = 0.f;   // per-lane partial row sums

    const int rl0 = w * 16 + (lane >> 2);
    const int q2 = (lane & 3) * 2;

    for (int tt = 0; tt < 16; tt++) {
        const int cur = tt & 1;
        if (tt + 1 < 16) {
            prefetch(tt + 1, cur ^ 1);
            CP_COMMIT();
            CP_WAIT(1);
        } else {
            CP_WAIT(0);
        }
        __syncthreads();

        const uint32_t kb = smem_u + AQB + cur * ASTG2 + kv_lane;
        const uint32_t vb = kb + AQB;
        const __half* Bs = (const __half*)(sm + AQB + cur * ASTG2 + 2 * AQB);

        // S = Q @ K^T (exp2 domain)
        float sacc[8][4];
        #pragma unroll
        for (int i = 0; i < 8; i++)
            sacc[i][0] = sacc[i][1] = sacc[i][2] = sacc[i][3] = 0.f;
        #pragma unroll
        for (int j = 0; j < 4; j++) {
            #pragma unroll
            for (int p = 0; p < 4; p++) {
                uint32_t bf[4];
                ldsm4(bf, kb + p * 2304 + j * 32);
                mma_f16(sacc[2 * p],     qf[j][0], qf[j][1], qf[j][2], qf[j][3], bf[0], bf[1]);
                mma_f16(sacc[2 * p + 1], qf[j][0], qf[j][1], qf[j][2], qf[j][3], bf[2], bf[3]);
            }
        }

        // p = exp2(s + bias'); per-lane partial row sums only
        #pragma unroll
        for (int nf = 0; nf < 8; nf++) {
            int cc = q2 + nf * 8;
            float2 ba = __half22float2(*(const __half2*)&Bs[rl0 * 72 + cc]);
            float2 bb = __half22float2(*(const __half2*)&Bs[(rl0 + 8) * 72 + cc]);
            sacc[nf][0] = ex2(sacc[nf][0] + ba.x);
            sacc[nf][1] = ex2(sacc[nf][1] + ba.y);
            sacc[nf][2] = ex2(sacc[nf][2] + bb.x);
            sacc[nf][3] = ex2(sacc[nf][3] + bb.y);
            l0 += sacc[nf][0] + sacc[nf][1];
            l1 += sacc[nf][2] + sacc[nf][3];
        }

        // O += P @ V
        #pragma unroll
        for (int j = 0; j < 4; j++) {
            uint32_t pa0 = packh2(sacc[2 * j][0],     sacc[2 * j][1]);
            uint32_t pa1 = packh2(sacc[2 * j][2],     sacc[2 * j][3]);
            uint32_t pa2 = packh2(sacc[2 * j + 1][0], sacc[2 * j + 1][1]);
            uint32_t pa3 = packh2(sacc[2 * j + 1][2], sacc[2 * j + 1][3]);
            #pragma unroll
            for (int p = 0; p < 4; p++) {
                uint32_t bf[4];
                ldsm4(bf, vb + p * 2304 + j * 32);
                mma_f16(oacc[2 * p],     pa0, pa1, pa2, pa3, bf[0], bf[1]);
                mma_f16(oacc[2 * p + 1], pa0, pa1, pa2, pa3, bf[2], bf[3]);
            }
        }
        __syncthreads();   // stage reads done before it is refilled
    }

    // epilogue: reduce row sums, normalize, head_mask, write
    l0 += __shfl_xor_sync(0xffffffffu, l0, 1);
    l0 += __shfl_xor_sync(0xffffffffu, l0, 2);
    l1 += __shfl_xor_sync(0xffffffffu, l1, 1);
    l1 += __shfl_xor_sync(0xffffffffu, l1, 2);
    const float hm = hmask[h];
    const float i0 = hm / l0, i1 = hm / l1;
    const int sA = s0 + rl0;
    float* o0 = out + ((size_t)b * SS + sA) * HID + h * DD + q2;
    float* o1 = out + ((size_t)b * SS + sA + 8) * HID + h * DD + q2;
    #pragma unroll
    for (int nf = 0; nf < 8; nf++) {
        *(float2*)(o0 + nf * 8) = make_float2(oacc[nf][0] * i0, oacc[nf][1] * i0);
        *(float2*)(o1 + nf * 8) = make_float2(oacc[nf][2] * i1, oacc[nf][3] * i1);
    }
}

// ---------------- launch ----------------------------------------------------
extern "C" void kernel_launch(void* const* d_in, const int* in_sizes, int n_in,
                              void* d_out, int out_size)
{
    const float* hs    = (const float*)d_in[0];
    const float* amask = (const float*)d_in[1];
    const float* hmask = (const float*)d_in[2];
    const float* rel1  = (const float*)d_in[3];
    const float* rel2  = (const float*)d_in[4];
    const float* Wq    = (const float*)d_in[5];
    const float* bq    = (const float*)d_in[6];
    const float* Wk    = (const float*)d_in[7];
    const float* bk    = (const float*)d_in[8];
    const float* Wv    = (const float*)d_in[9];
    const float* bv    = (const float*)d_in[10];
    float* out = (float*)d_out;

    const int smem_proj = 2 * PSTG;              // 71680
    cudaFuncSetAttribute(proj_prep, cudaFuncAttributeMaxDynamicSharedMemorySize, smem_proj);
    cudaFuncSetAttribute(attn_kernel, cudaFuncAttributeMaxDynamicSharedMemorySize, SMEM_ATTN);

    to_half<<<dim3(768, 4), 256>>>(hs, Wq, Wk, Wv);

    proj_prep<<<PROJ_BLOCKS + PREP_BLOCKS, 256, smem_proj>>>(
        bq, bk, bv, rel1, rel2, amask);

    dim3 ga(SS / 64, BB * HH);                // (16,24)
    attn_kernel<<<ga, 128, SMEM_ATTN>>>(hmask, out);
}